// round 2
// baseline (speedup 1.0000x reference)
#include <cuda_runtime.h>
#include <cstdint>

// ---------------- problem constants ----------------
#define TOTAL   340704u        // 16224 + 64896 + 259584 candidates
#define OFF1    16224u
#define OFF2    81120u
#define KSEL    512u
#define NBOX    1536
#define NWORD   24             // 1536/64 mask words per row
#define NB      128            // persistent blocks (single wave on 148+ SMs)
#define NT      256
#define GSZ     (NB*NT)

typedef unsigned long long u64;
typedef uint32_t u32;

// ---------------- device scratch (static, allocation-free) ----------------
__device__ u32  g_keys[TOTAL];
__device__ u32  g_hist [3*65536];
__device__ u32  g_hist2[3*65536];
__device__ u32  g_validCount[3];
__device__ u32  g_binB[3];
__device__ u32  g_countAboveB[3];
__device__ u32  g_threshKey[3];
__device__ u32  g_needEq[3];
__device__ u32  g_selCount[3];
__device__ u32  g_eqCount[3];
__device__ u64  g_sel[3*512];
__device__ u32  g_eq[3*262144];
__device__ u64  g_sorted[NBOX];
__device__ float g_boxes[NBOX*9];
__device__ float g_nmsb[NBOX*5];     // x1,y1,x2,y2,area
__device__ int   g_valid[NBOX];
__device__ u64  g_mask[NBOX*NWORD];
__device__ u32  g_keep[NBOX];

// ---------------- software grid barrier (CG-style, single-wave safe) -------
__device__ u32           g_bar_cnt;        // zero-initialized, self-resetting
__device__ volatile u32  g_bar_gen;

__device__ __forceinline__ void gridbar() {
    __syncthreads();
    if (threadIdx.x == 0) {
        __threadfence();                       // release prior writes
        u32 gen = g_bar_gen;
        if (atomicAdd(&g_bar_cnt, 1u) == (u32)(NB - 1)) {
            g_bar_cnt = 0u;
            __threadfence();
            g_bar_gen = gen + 1u;              // release
        } else {
            while (g_bar_gen == gen) __nanosleep(128);
        }
        __threadfence();                       // acquire
    }
    __syncthreads();
}

// ---------------- radix-select scan phase (per-scale, one block) -----------
__device__ void scan_phase(int pass, int s, unsigned char* shraw) {
    u32 t = threadIdx.x;
    u32 K = 0; const u32* hist = nullptr;
    bool active = true;
    if (pass == 0) {
        if (g_validCount[s] < KSEL) {
            if (t == 0) { g_binB[s] = 0xFFFFFFFFu; g_threshKey[s] = 0u; g_needEq[s] = 0u; }
            active = false;
        } else { K = KSEL; hist = g_hist + s*65536; }
    } else {
        if (g_binB[s] == 0xFFFFFFFFu) active = false;
        else { K = KSEL - g_countAboveB[s]; hist = g_hist2 + s*65536; }
    }
    if (!active) return;                       // block-uniform
    u32* ssum = (u32*)shraw;
    u32 base = t * 256u;
    u32 local = 0u;
    #pragma unroll 16
    for (int k = 0; k < 256; k++) local += hist[base + k];
    ssum[t] = local;
    __syncthreads();
    #pragma unroll
    for (u32 off = 1; off < 256; off <<= 1) {  // inclusive suffix scan
        u32 add = (t + off < 256u) ? ssum[t + off] : 0u;
        __syncthreads();
        ssum[t] += add;
        __syncthreads();
    }
    u32 S = ssum[t];
    u32 Snext = (t < 255u) ? ssum[t + 1] : 0u;
    if (S >= K && Snext < K) {
        u32 cum = Snext;
        for (int k = 255; k >= 0; k--) {
            u32 hc = hist[base + k];
            cum += hc;
            if (cum >= K) {
                u32 bin = base + (u32)k;
                u32 above = cum - hc;
                if (pass == 0) { g_binB[s] = bin; g_countAboveB[s] = above; }
                else { g_threshKey[s] = (g_binB[s] << 16) | bin; g_needEq[s] = K - above; }
                break;
            }
        }
    }
}

// ---------------- the single persistent kernel ----------------
__global__ __launch_bounds__(NT, 1) void mega(
    const float* __restrict__ o13, const float* __restrict__ o26,
    const float* __restrict__ o52,
    const float* __restrict__ a13, const float* __restrict__ a26,
    const float* __restrict__ a52,
    float* __restrict__ out)
{
    __shared__ __align__(16) unsigned char shraw[30976];
    const u32 tid  = threadIdx.x;
    const u32 blk  = blockIdx.x;
    const u32 gtid = blk * NT + tid;

    // ---- P0: zero per-iteration state ----
    for (u32 i = gtid; i < 3u*65536u; i += GSZ) { g_hist[i] = 0u; g_hist2[i] = 0u; }
    if (gtid < 3u) { g_validCount[gtid] = 0u; g_selCount[gtid] = 0u; g_eqCount[gtid] = 0u; }
    gridbar();

    // ---- P1: scores -> keys + 16-bit histogram ----
    {
        u32* svc = (u32*)shraw;
        if (tid < 3u) svc[tid] = 0u;
        __syncthreads();
        for (u32 i = gtid; i < TOTAL; i += GSZ) {
            const float* p; u32 loc, nhw, hw2; int s;
            if (i < OFF1)      { p = o13; loc = i;        nhw = 5408u;  hw2 = 169u;  s = 0; }
            else if (i < OFF2) { p = o26; loc = i - OFF1; nhw = 21632u; hw2 = 676u;  s = 1; }
            else               { p = o52; loc = i - OFF2; nhw = 86528u; hw2 = 2704u; s = 2; }
            u32 a = loc / nhw, r = loc - a*nhw;
            u32 n = r / hw2,  hw = r - n*hw2;
            float x   = p[(size_t)(n*255u + a*85u)*hw2 + hw];
            float obj = 1.f / (1.f + expf(-x));
            u32 key = 0u;
            if (obj > 0.6f) {
                key = __float_as_uint(obj) | 0x80000000u;
                atomicAdd(&g_hist[(u32)s*65536u + (key >> 16)], 1u);
                atomicAdd(&svc[s], 1u);
            }
            g_keys[i] = key;
        }
        __syncthreads();
        if (tid < 3u && svc[tid]) atomicAdd(&g_validCount[tid], svc[tid]);
    }
    gridbar();

    // ---- P2: locate threshold upper-16 bin ----
    if (blk < 3u) scan_phase(0, (int)blk, shraw);
    gridbar();

    // ---- P3: second-level histogram ----
    for (u32 i = gtid; i < TOTAL; i += GSZ) {
        int s = (i < OFF1) ? 0 : (i < OFF2) ? 1 : 2;
        u32 key = g_keys[i];
        if ((key >> 16) == g_binB[s])
            atomicAdd(&g_hist2[(u32)s*65536u + (key & 0xFFFFu)], 1u);
    }
    gridbar();

    // ---- P4: exact 32-bit threshold key ----
    if (blk < 3u) scan_phase(1, (int)blk, shraw);
    gridbar();

    // ---- P5: compact winners + equal-key pool ----
    for (u32 i = gtid; i < TOTAL; i += GSZ) {
        u32 key = g_keys[i];
        if (key == 0u) continue;
        u32 s, loc, nhw;
        if (i < OFF1)      { s = 0; loc = i;        nhw = 5408u;  }
        else if (i < OFF2) { s = 1; loc = i - OFF1; nhw = 21632u; }
        else               { s = 2; loc = i - OFF2; nhw = 86528u; }
        u32 tk = g_threshKey[s];
        u32 a = loc / nhw, r = loc - a*nhw;
        u32 orig = r*3u + a;                      // reference flatten order
        if (key > tk) {
            u32 pos = atomicAdd(&g_selCount[s], 1u);
            g_sel[s*512u + pos] = ((u64)key << 32) | orig;
        } else if (key == tk && g_needEq[s] != 0u) {
            u32 pos = atomicAdd(&g_eqCount[s], 1u);
            g_eq[s*262144u + pos] = orig;
        }
    }
    gridbar();

    // ---- P6: resolve equal-key ties (lowest index first) ----
    if (blk < 3u) {
        int s = (int)blk;
        u32 need = g_needEq[s];
        if (need) {
            u32 n  = g_eqCount[s];
            u32 tk = g_threshKey[s];
            const u32* eq = &g_eq[(u32)s * 262144u];
            u32* scnt = (u32*)shraw;
            u32 T = 0xFFFFFFFFu;
            if (n > need) {                       // binary search need-th smallest index
                u32 lo = 0u, hi = 262143u;
                while (lo < hi) {
                    u32 mid = (lo + hi) >> 1;
                    if (tid == 0) *scnt = 0u;
                    __syncthreads();
                    u32 c = 0u;
                    for (u32 j = tid; j < n; j += NT) if (eq[j] <= mid) c++;
                    if (c) atomicAdd(scnt, c);
                    __syncthreads();
                    u32 total = *scnt;
                    __syncthreads();
                    if (total >= need) hi = mid; else lo = mid + 1u;
                }
                T = lo;
            }
            for (u32 j = tid; j < n; j += NT) {
                u32 idx = eq[j];
                if (idx <= T) {
                    u32 pos = atomicAdd(&g_selCount[s], 1u);
                    g_sel[(u32)s*512u + pos] = ((u64)tk << 32) | idx;
                }
            }
        }
    }
    gridbar();

    // ---- P7: global bitonic sort (score desc, concat-pos asc), block 0 ----
    if (blk == 0u) {
        u64* sm = (u64*)shraw;
        for (int j = (int)tid; j < 2048; j += NT) {
            u64 v = 0ull;
            if (j < NBOX) {
                int s = j >> 9, pp = j & 511;
                if ((u32)pp < g_selCount[s]) {
                    u64 e = g_sel[s*512 + pp];
                    u32 key  = (u32)(e >> 32);
                    u32 gidx = ((s == 0) ? 0u : (s == 1) ? OFF1 : OFF2) + (u32)e;
                    v = ((u64)key << 32) | (u32)(~gidx);
                }
            }
            sm[j] = v;
        }
        __syncthreads();
        for (int k = 2; k <= 2048; k <<= 1)
            for (int j = k >> 1; j > 0; j >>= 1) {
                for (int i = (int)tid; i < 2048; i += NT) {
                    int ixj = i ^ j;
                    if (ixj > i) {
                        bool desc = ((i & k) == 0);
                        u64 x = sm[i], y = sm[ixj];
                        if (desc ? (x < y) : (x > y)) { sm[i] = y; sm[ixj] = x; }
                    }
                }
                __syncthreads();
            }
        for (int j = (int)tid; j < NBOX; j += NT) g_sorted[j] = sm[j];
    }
    gridbar();

    // ---- P8: decode winners (one warp per box) ----
    {
        u32 warpid = blk * (NT/32u) + (tid >> 5);
        u32 lane   = tid & 31u;
        for (u32 r = warpid; r < NBOX; r += NB * (NT/32u)) {
            u64 e = g_sorted[r];
            u32 key = (u32)(e >> 32);
            if (key == 0u) {
                if (lane == 0) {
                    #pragma unroll
                    for (int k = 0; k < 9; k++) g_boxes[r*9 + k] = 0.f;
                    #pragma unroll
                    for (int k = 0; k < 5; k++) g_nmsb[r*5 + k] = 0.f;
                    g_valid[r] = 0;
                }
                continue;
            }
            u32 gidx = ~(u32)e;
            const float* p; const float* anc; int H; float ts; u32 loc;
            if (gidx < OFF1)      { p = o13; anc = a13; H = 13; ts = 32.f; loc = gidx; }
            else if (gidx < OFF2) { p = o26; anc = a26; H = 26; ts = 16.f; loc = gidx - OFF1; }
            else                  { p = o52; anc = a52; H = 52; ts = 8.f;  loc = gidx - OFF2; }
            u32 a = loc % 3u; u32 q = loc / 3u;
            u32 w = q % (u32)H; q /= (u32)H;
            u32 h = q % (u32)H; u32 n = q / (u32)H;
            int HW = H * H;
            const float* base = p + (size_t)(n*255u + a*85u)*HW + h*H + w;
            float bv = -1e30f; int bc = 1 << 30;        // argmax 80 classes
            for (int c = (int)lane; c < 80; c += 32) {
                float v = base[(5 + c) * HW];
                if (v > bv) { bv = v; bc = c; }
            }
            #pragma unroll
            for (int off = 16; off; off >>= 1) {
                float ov = __shfl_down_sync(0xffffffffu, bv, off);
                int   oc = __shfl_down_sync(0xffffffffu, bc, off);
                if (ov > bv || (ov == bv && oc < bc)) { bv = ov; bc = oc; }
            }
            if (lane == 0) {
                float v1 = base[HW], v2 = base[2*HW], v3 = base[3*HW], v4 = base[4*HW];
                float obj = __uint_as_float(key ^ 0x80000000u);
                float cx = ((float)w + v1) * ts / 416.0f;
                float cy = ((float)h + v2) * ts / 416.0f;
                float bw = anc[a*2 + 0] * expf(v3) / 416.0f;
                float bh = anc[a*2 + 1] * expf(v4) / 416.0f;
                float* B = &g_boxes[r*9];
                B[0] = (float)n; B[1] = cx; B[2] = cy; B[3] = bw; B[4] = bh;
                B[5] = obj; B[6] = (float)bc; B[7] = (float)h; B[8] = (float)w;
                float x1 = cx - bw*0.5f, y1 = cy - bh*0.5f;
                float x2 = cx + bw*0.5f, y2 = cy + bh*0.5f;
                float area = fmaxf(x2 - x1, 0.f) * fmaxf(y2 - y1, 0.f);
                float* Nn = &g_nmsb[r*5];
                Nn[0] = x1; Nn[1] = y1; Nn[2] = x2; Nn[3] = y2; Nn[4] = area;
                g_valid[r] = 1;
            }
        }
    }
    gridbar();

    // ---- P9: suppression bitmask (iou inter/min > 0.7, col > row) ----
    {
        float* cb5 = (float*)shraw;                 // all 1536 boxes cached
        for (u32 i = tid; i < NBOX*5u; i += NT) cb5[i] = g_nmsb[i];
        __syncthreads();
        for (u32 task = tid; task < 12u*24u; task += NT) {
            u32 r  = blk*12u + task / 24u;
            u32 cw = task % 24u;
            float x1 = cb5[r*5+0], y1 = cb5[r*5+1], x2 = cb5[r*5+2],
                  y2 = cb5[r*5+3], ar = cb5[r*5+4];
            u64 bits = 0ull;
            u32 cbase = cw * 64u;
            #pragma unroll 4
            for (u32 j = 0; j < 64u; j++) {
                u32 cc = cbase + j;
                if (cc > r) {
                    const float* c = &cb5[cc*5];
                    float ix = fmaxf(fminf(x2, c[2]) - fmaxf(x1, c[0]), 0.f);
                    float iy = fmaxf(fminf(y2, c[3]) - fmaxf(y1, c[1]), 0.f);
                    float iou = (ix * iy) / fmaxf(fminf(ar, c[4]), 1e-9f);
                    if (iou > 0.7f) bits |= (1ull << j);
                }
            }
            g_mask[r*NWORD + cw] = bits;
        }
    }
    gridbar();

    // ---- P10: serial greedy scan (block 0) ----
    if (blk == 0u) {
        u64* tile = (u64*)shraw;                             // 12288 B
        unsigned char* keepArr = (unsigned char*)(shraw + 12288);
        unsigned char* svalid  = (unsigned char*)(shraw + 12288 + 1536);
        for (u32 i = tid; i < NBOX; i += NT) svalid[i] = (unsigned char)g_valid[i];
        u64 remv = 0ull;                                     // lanes 0..23 hold words
        __syncthreads();
        for (int c = 0; c < NWORD; c++) {
            for (u32 k = tid; k < 64u*NWORD; k += NT)
                tile[k] = g_mask[(size_t)(c*64)*NWORD + k];
            __syncthreads();
            if (tid < 32u) {
                u64 cur = __shfl_sync(0xffffffffu, remv, c);
                u64 keptbits = 0ull;
                if (tid == 0) {
                    for (int j = 0; j < 64; j++) {
                        int i = c*64 + j;
                        bool kept = svalid[i] && !((cur >> j) & 1ull);
                        if (kept) { cur |= tile[j*NWORD + c]; keptbits |= 1ull << j; }
                        keepArr[i] = kept;
                    }
                }
                keptbits = __shfl_sync(0xffffffffu, keptbits, 0);
                if (tid < NWORD) {
                    u64 acc = 0ull;
                    for (int j = 0; j < 64; j++)
                        if ((keptbits >> j) & 1ull) acc |= tile[j*NWORD + tid];
                    remv |= acc;
                }
            }
            __syncthreads();
        }
        for (u32 i = tid; i < NBOX; i += NT) g_keep[i] = keepArr[i];
    }
    gridbar();

    // ---- P11: masked output write ----
    for (u32 e = gtid; e < NBOX*9u; e += GSZ) {
        u32 r = e / 9u;
        out[e] = g_boxes[e] * (g_keep[r] ? 1.f : 0.f);
    }
}

// ---------------- launcher: ONE graph node ----------------
extern "C" void kernel_launch(void* const* d_in, const int* in_sizes, int n_in,
                              void* d_out, int out_size) {
    const float* o13 = (const float*)d_in[0];
    const float* o26 = (const float*)d_in[1];
    const float* o52 = (const float*)d_in[2];
    const float* a13 = (const float*)d_in[3];
    const float* a26 = (const float*)d_in[4];
    const float* a52 = (const float*)d_in[5];
    float* out = (float*)d_out;
    mega<<<NB, NT>>>(o13, o26, o52, a13, a26, a52, out);
    (void)in_sizes; (void)n_in; (void)out_size;
}

// round 3
// speedup vs baseline: 2.0219x; 2.0219x over previous
#include <cuda_runtime.h>
#include <cstdint>

// ---------------- problem constants ----------------
#define TOTAL   340704u        // 16224 + 64896 + 259584 candidates
#define OFF1    16224u
#define OFF2    81120u
#define KSEL    512u
#define NBOX    1536
#define NWORD   24             // 1536/64 mask words per row
#define HBASE   0xBF19u        // lowest possible key>>16 for obj in (0.6, 1.0]
#define HBINS   128u           // covers [0xBF19, 0xBF99) — actual range ends 0xBF80

typedef unsigned long long u64;
typedef uint32_t u32;

// ---------------- device scratch (static, allocation-free) ----------------
__device__ u32   g_keys[TOTAL];
__device__ u32   g_hist [3*HBINS];
__device__ u32   g_hist2[3*65536];
__device__ u32   g_validCount[3];
__device__ u32   g_binB[3];
__device__ u32   g_countAboveB[3];
__device__ u32   g_threshKey[3];
__device__ u32   g_needEq[3];
__device__ u32   g_selCount[3];
__device__ u32   g_eqCount[3];
__device__ u64   g_sel[3*512];
__device__ u32   g_eq[3*262144];
__device__ u64   g_sorted[NBOX];
__device__ float g_boxes[NBOX*9];
__device__ float g_nmsb[NBOX*5];     // x1,y1,x2,y2,area
__device__ int   g_valid[NBOX];
__device__ u64   g_mask[NBOX*NWORD];

// ---------------- K0: zero per-iteration state ----------------
__global__ void k_zero() {
    u32 i = blockIdx.x*blockDim.x + threadIdx.x;
    if (i < 3u*65536u) g_hist2[i] = 0u;
    if (i < 3u*HBINS)  g_hist[i]  = 0u;
    if (i < 3u) { g_validCount[i]=0u; g_selCount[i]=0u; g_eqCount[i]=0u; }
}

// ---------------- K1: scores -> keys + 128-bin shared histogram ----------------
__global__ __launch_bounds__(256) void k_scores(const float* __restrict__ o13,
                                                const float* __restrict__ o26,
                                                const float* __restrict__ o52) {
    __shared__ u32 sh[3*HBINS];
    __shared__ u32 svc[3];
    for (u32 b = threadIdx.x; b < 3u*HBINS; b += 256u) sh[b] = 0u;
    if (threadIdx.x < 3u) svc[threadIdx.x] = 0u;
    __syncthreads();
    u32 stride = gridDim.x * blockDim.x;
    for (u32 i = blockIdx.x*256u + threadIdx.x; i < TOTAL; i += stride) {
        float x; int s;
        if (i < OFF1) {                 // H=13, HW=169, NHW=5408 (compile-time divisors)
            u32 loc = i;
            u32 a = loc / 5408u, r = loc - a*5408u;
            u32 n = r / 169u,  hw = r - n*169u;
            x = o13[(n*255u + a*85u)*169u + hw]; s = 0;
        } else if (i < OFF2) {          // H=26, HW=676, NHW=21632
            u32 loc = i - OFF1;
            u32 a = loc / 21632u, r = loc - a*21632u;
            u32 n = r / 676u,  hw = r - n*676u;
            x = o26[(n*255u + a*85u)*676u + hw]; s = 1;
        } else {                        // H=52, HW=2704, NHW=86528
            u32 loc = i - OFF2;
            u32 a = loc / 86528u, r = loc - a*86528u;
            u32 n = r / 2704u, hw = r - n*2704u;
            x = o52[(n*255u + a*85u)*2704u + hw]; s = 2;
        }
        float obj = 1.f / (1.f + expf(-x));
        u32 key = 0u;
        if (obj > 0.6f) {
            key = __float_as_uint(obj) | 0x80000000u;
            atomicAdd(&sh[(u32)s*HBINS + ((key >> 16) - HBASE)], 1u);
            atomicAdd(&svc[s], 1u);
        }
        g_keys[i] = key;
    }
    __syncthreads();
    for (u32 b = threadIdx.x; b < 3u*HBINS; b += 256u) {
        u32 v = sh[b];
        if (v) atomicAdd(&g_hist[b], v);
    }
    if (threadIdx.x < 3u && svc[threadIdx.x]) atomicAdd(&g_validCount[threadIdx.x], svc[threadIdx.x]);
}

// ---------------- K2: locate threshold upper-16 bin (128 bins) ----------------
__global__ void k_scan1() {
    int s = blockIdx.x;
    u32 t = threadIdx.x;                     // 128 threads, one bin each
    if (g_validCount[s] < KSEL) {
        if (t == 0) { g_binB[s] = 0xFFFFFFFFu; g_threshKey[s] = 0u; g_needEq[s] = 0u; }
        return;
    }
    __shared__ u32 ss[HBINS];
    ss[t] = g_hist[(u32)s*HBINS + t];
    __syncthreads();
    for (u32 off = 1; off < HBINS; off <<= 1) {   // inclusive suffix scan
        u32 add = (t + off < HBINS) ? ss[t + off] : 0u;
        __syncthreads();
        ss[t] += add;
        __syncthreads();
    }
    u32 S = ss[t];
    u32 Sn = (t < HBINS - 1u) ? ss[t + 1] : 0u;
    if (S >= KSEL && Sn < KSEL) {
        g_binB[s] = HBASE + t;
        g_countAboveB[s] = Sn;
    }
}

// ---------------- K3: second-level histogram (low 16 bits) ----------------
__global__ void k_hist2() {
    u32 i = blockIdx.x*blockDim.x + threadIdx.x;
    if (i >= TOTAL) return;
    int s = (i < OFF1) ? 0 : (i < OFF2) ? 1 : 2;
    u32 key = g_keys[i];
    if ((key >> 16) == g_binB[s])
        atomicAdd(&g_hist2[(u32)s*65536u + (key & 0xFFFFu)], 1u);
}

// ---------------- K4: exact 32-bit threshold key ----------------
__global__ __launch_bounds__(1024) void k_scan2() {
    int s = blockIdx.x;
    u32 t = threadIdx.x;
    if (g_binB[s] == 0xFFFFFFFFu) return;
    u32 K = KSEL - g_countAboveB[s];
    const u32* hist = g_hist2 + (u32)s*65536u;
    __shared__ u32 ssum[1024];
    u32 base = t * 64u;
    u32 local = 0u;
    #pragma unroll 16
    for (int k = 0; k < 64; k++) local += hist[base + k];
    ssum[t] = local;
    __syncthreads();
    for (u32 off = 1; off < 1024; off <<= 1) {    // inclusive suffix scan
        u32 add = (t + off < 1024u) ? ssum[t + off] : 0u;
        __syncthreads();
        ssum[t] += add;
        __syncthreads();
    }
    u32 S = ssum[t];
    u32 Sn = (t < 1023u) ? ssum[t + 1] : 0u;
    if (S >= K && Sn < K) {
        u32 cum = Sn;
        for (int k = 63; k >= 0; k--) {
            u32 hc = hist[base + k];
            cum += hc;
            if (cum >= K) {
                u32 bin = base + (u32)k;
                g_threshKey[s] = (g_binB[s] << 16) | bin;
                g_needEq[s] = K - (cum - hc);
                break;
            }
        }
    }
}

// ---------------- K5: compact winners + equal-key pool ----------------
__global__ void k_compact() {
    u32 i = blockIdx.x*blockDim.x + threadIdx.x;
    if (i >= TOTAL) return;
    u32 key = g_keys[i];
    if (key == 0u) return;
    u32 s, orig;
    if (i < OFF1) {
        s = 0; u32 loc = i;
        u32 a = loc / 5408u, r = loc - a*5408u;
        orig = r*3u + a;
    } else if (i < OFF2) {
        s = 1; u32 loc = i - OFF1;
        u32 a = loc / 21632u, r = loc - a*21632u;
        orig = r*3u + a;
    } else {
        s = 2; u32 loc = i - OFF2;
        u32 a = loc / 86528u, r = loc - a*86528u;
        orig = r*3u + a;
    }
    u32 tk = g_threshKey[s];
    if (key > tk) {
        u32 pos = atomicAdd(&g_selCount[s], 1u);
        g_sel[s*512u + pos] = ((u64)key << 32) | orig;
    } else if (key == tk && g_needEq[s] != 0u) {
        u32 pos = atomicAdd(&g_eqCount[s], 1u);
        g_eq[s*262144u + pos] = orig;
    }
}

// ---------------- K6: resolve equal-key ties (lowest index first) ----------------
__global__ void k_ties() {
    int s = blockIdx.x;
    u32 need = g_needEq[s];
    if (need == 0u) return;
    u32 n  = g_eqCount[s];
    u32 tk = g_threshKey[s];
    const u32* eq = &g_eq[(u32)s * 262144u];
    __shared__ u32 scnt;
    u32 T = 0xFFFFFFFFu;
    if (n > need) {                       // binary search need-th smallest index
        u32 lo = 0u, hi = 262143u;
        while (lo < hi) {
            u32 mid = (lo + hi) >> 1;
            if (threadIdx.x == 0) scnt = 0u;
            __syncthreads();
            u32 c = 0u;
            for (u32 j = threadIdx.x; j < n; j += blockDim.x)
                if (eq[j] <= mid) c++;
            if (c) atomicAdd(&scnt, c);
            __syncthreads();
            u32 total = scnt;
            __syncthreads();
            if (total >= need) hi = mid; else lo = mid + 1u;
        }
        T = lo;
    }
    __syncthreads();
    for (u32 j = threadIdx.x; j < n; j += blockDim.x) {
        u32 idx = eq[j];
        if (idx <= T) {
            u32 pos = atomicAdd(&g_selCount[s], 1u);
            g_sel[(u32)s*512u + pos] = ((u64)tk << 32) | idx;
        }
    }
}

// ---------------- K7: global bitonic sort (score desc, concat-pos asc) ----------------
__global__ __launch_bounds__(1024) void k_sort() {
    __shared__ u64 sm[2048];
    int t = threadIdx.x;
    const u32 offc[3] = {0u, OFF1, OFF2};
    for (int j = t; j < 2048; j += 1024) {
        u64 v = 0ull;
        if (j < NBOX) {
            int s = j >> 9, p = j & 511;
            if ((u32)p < g_selCount[s]) {
                u64 e = g_sel[s*512 + p];
                u32 key  = (u32)(e >> 32);
                u32 gidx = offc[s] + (u32)e;
                v = ((u64)key << 32) | (u32)(~gidx);
            }
        }
        sm[j] = v;
    }
    __syncthreads();
    for (int k = 2; k <= 2048; k <<= 1)
        for (int j = k >> 1; j > 0; j >>= 1) {
            for (int i = t; i < 2048; i += 1024) {
                int ixj = i ^ j;
                if (ixj > i) {
                    bool desc = ((i & k) == 0);
                    u64 x = sm[i], y = sm[ixj];
                    if (desc ? (x < y) : (x > y)) { sm[i] = y; sm[ixj] = x; }
                }
            }
            __syncthreads();
        }
    for (int j = t; j < NBOX; j += 1024) g_sorted[j] = sm[j];
}

// ---------------- K8: decode winners (one warp per box) ----------------
__global__ void k_decode(const float* __restrict__ o13, const float* __restrict__ o26,
                         const float* __restrict__ o52,
                         const float* __restrict__ a13, const float* __restrict__ a26,
                         const float* __restrict__ a52) {
    int r = (blockIdx.x * blockDim.x + threadIdx.x) >> 5;
    int lane = threadIdx.x & 31;
    if (r >= NBOX) return;
    u64 e = g_sorted[r];
    u32 key = (u32)(e >> 32);
    if (key == 0u) {
        if (lane == 0) {
            #pragma unroll
            for (int k = 0; k < 9; k++) g_boxes[r*9+k] = 0.f;
            #pragma unroll
            for (int k = 0; k < 5; k++) g_nmsb[r*5+k] = 0.f;
            g_valid[r] = 0;
        }
        return;
    }
    u32 gidx = ~(u32)e;
    const float* p; const float* anc; int H; float ts; u32 loc;
    if (gidx < OFF1)      { p=o13; anc=a13; H=13; ts=32.f; loc=gidx; }
    else if (gidx < OFF2) { p=o26; anc=a26; H=26; ts=16.f; loc=gidx-OFF1; }
    else                  { p=o52; anc=a52; H=52; ts=8.f;  loc=gidx-OFF2; }
    u32 a = loc % 3u; u32 q = loc / 3u;
    u32 w = q % (u32)H; q /= (u32)H;
    u32 h = q % (u32)H; u32 n = q / (u32)H;
    int HW = H*H;
    const float* base = p + (size_t)(n*255u + a*85u)*HW + h*H + w;
    // argmax over 80 classes, first-max tie-break
    float bv = -1e30f; int bc = 1 << 30;
    for (int c = lane; c < 80; c += 32) {
        float v = base[(5 + c) * HW];
        if (v > bv) { bv = v; bc = c; }
    }
    #pragma unroll
    for (int off = 16; off; off >>= 1) {
        float ov = __shfl_down_sync(0xffffffffu, bv, off);
        int   oc = __shfl_down_sync(0xffffffffu, bc, off);
        if (ov > bv || (ov == bv && oc < bc)) { bv = ov; bc = oc; }
    }
    if (lane == 0) {
        float v1 = base[HW], v2 = base[2*HW], v3 = base[3*HW], v4 = base[4*HW];
        float obj = __uint_as_float(key ^ 0x80000000u);
        float cx = ((float)w + v1) * ts / 416.0f;
        float cy = ((float)h + v2) * ts / 416.0f;
        float bw = anc[a*2+0] * expf(v3) / 416.0f;
        float bh = anc[a*2+1] * expf(v4) / 416.0f;
        float* B = &g_boxes[r*9];
        B[0]=(float)n; B[1]=cx; B[2]=cy; B[3]=bw; B[4]=bh;
        B[5]=obj; B[6]=(float)bc; B[7]=(float)h; B[8]=(float)w;
        float x1 = cx - bw*0.5f, y1 = cy - bh*0.5f;
        float x2 = cx + bw*0.5f, y2 = cy + bh*0.5f;
        float area = fmaxf(x2-x1, 0.f) * fmaxf(y2-y1, 0.f);
        float* Nn = &g_nmsb[r*5];
        Nn[0]=x1; Nn[1]=y1; Nn[2]=x2; Nn[3]=y2; Nn[4]=area;
        g_valid[r] = 1;
    }
}

// ---------------- K9: suppression bitmask (iou inter/min > 0.7, col > row) ----------------
__global__ void k_mask() {
    int cb = blockIdx.x, rb = blockIdx.y;
    __shared__ float c0[64], c1[64], c2[64], c3[64], ca[64];
    int t = threadIdx.x;
    int c = cb*64 + t;
    c0[t]=g_nmsb[c*5+0]; c1[t]=g_nmsb[c*5+1]; c2[t]=g_nmsb[c*5+2];
    c3[t]=g_nmsb[c*5+3]; ca[t]=g_nmsb[c*5+4];
    __syncthreads();
    int r = rb*64 + t;
    float x1=g_nmsb[r*5+0], y1=g_nmsb[r*5+1], x2=g_nmsb[r*5+2],
          y2=g_nmsb[r*5+3], ar=g_nmsb[r*5+4];
    u64 bits = 0ull;
    #pragma unroll 4
    for (int j = 0; j < 64; j++) {
        int cc = cb*64 + j;
        if (cc > r) {
            float ix = fmaxf(fminf(x2, c2[j]) - fmaxf(x1, c0[j]), 0.f);
            float iy = fmaxf(fminf(y2, c3[j]) - fmaxf(y1, c1[j]), 0.f);
            float iou = (ix * iy) / fmaxf(fminf(ar, ca[j]), 1e-9f);
            if (iou > 0.7f) bits |= (1ull << j);
        }
    }
    g_mask[r*NWORD + cb] = bits;
}

// ---------------- K10: greedy scan — register-resident serial closure ----------------
// Per 64-box chunk: thread 0 preloads the chunk's diagonal 64x64 block column
// into 64 registers (fully unrolled, static indices) so the serial dependence
// is a pure ALU chain. Cross-chunk suppression is OR-folded per word by the
// first 24 lanes over the *set* kept bits only. Tiles are double-buffered:
// warps 1..7 prefetch chunk c+1 while warp 0 processes chunk c.
__global__ __launch_bounds__(256) void k_nms_out(float* __restrict__ out) {
    __shared__ u64 tile[2][64*NWORD];      // 2 x 12 KB
    __shared__ u64 svalidw[NWORD];
    __shared__ u64 skeep[NWORD];
    int tid = threadIdx.x;
    if (tid < NWORD) {
        u64 v = 0ull;
        for (int j = 0; j < 64; j++) if (g_valid[tid*64 + j]) v |= 1ull << j;
        svalidw[tid] = v;
    }
    for (int k = tid; k < 64*NWORD; k += 256)
        tile[0][k] = g_mask[k];
    __syncthreads();
    u64 remv = 0ull;                        // lane w (w<NWORD) holds remv word w
    for (int c = 0; c < NWORD; c++) {
        if (tid >= 32 && c + 1 < NWORD) {   // prefetch next chunk
            for (int k = tid - 32; k < 64*NWORD; k += 224)
                tile[(c+1)&1][k] = g_mask[(size_t)(c+1)*(64*NWORD) + k];
        }
        if (tid < 32) {
            u64* T = tile[c&1];
            u64 cur = __shfl_sync(0xffffffffu, remv, c);
            u64 keptbits = 0ull;
            if (tid == 0) {
                u64 validw = svalidw[c];
                u64 rows[64];
                #pragma unroll
                for (int j = 0; j < 64; j++) rows[j] = T[j*NWORD + c];
                #pragma unroll
                for (int j = 0; j < 64; j++) {
                    u64 b = 1ull << j;
                    if ((validw & b) && !(cur & b)) { cur |= rows[j]; keptbits |= b; }
                }
                skeep[c] = keptbits;
            }
            keptbits = __shfl_sync(0xffffffffu, keptbits, 0);
            if (tid < NWORD) {
                u64 kb = keptbits, acc = 0ull;
                while (kb) {
                    int j = __ffsll((long long)kb) - 1;
                    kb &= kb - 1ull;
                    acc |= T[j*NWORD + tid];
                }
                remv |= acc;
            }
        }
        __syncthreads();
    }
    for (int e = tid; e < NBOX*9; e += 256) {
        int r = e / 9;
        out[e] = g_boxes[e] * (((skeep[r >> 6] >> (r & 63)) & 1ull) ? 1.f : 0.f);
    }
}

// ---------------- launcher ----------------
extern "C" void kernel_launch(void* const* d_in, const int* in_sizes, int n_in,
                              void* d_out, int out_size) {
    const float* o13 = (const float*)d_in[0];
    const float* o26 = (const float*)d_in[1];
    const float* o52 = (const float*)d_in[2];
    const float* a13 = (const float*)d_in[3];
    const float* a26 = (const float*)d_in[4];
    const float* a52 = (const float*)d_in[5];
    float* out = (float*)d_out;

    int gridAll = (int)((TOTAL + 255u) / 256u);
    k_zero   <<<768, 256>>>();
    k_scores <<<256, 256>>>(o13, o26, o52);
    k_scan1  <<<3, 128>>>();
    k_hist2  <<<gridAll, 256>>>();
    k_scan2  <<<3, 1024>>>();
    k_compact<<<gridAll, 256>>>();
    k_ties   <<<3, 256>>>();
    k_sort   <<<1, 1024>>>();
    k_decode <<<192, 256>>>(o13, o26, o52, a13, a26, a52);
    k_mask   <<<dim3(24,24), 64>>>();
    k_nms_out<<<1, 256>>>(out);
    (void)in_sizes; (void)n_in; (void)out_size;
}

// round 4
// speedup vs baseline: 2.4374x; 1.2055x over previous
#include <cuda_runtime.h>
#include <cstdint>

// ---------------- problem constants ----------------
#define TOTAL   340704u        // 16224 + 64896 + 259584 candidates
#define OFF1    16224u
#define OFF2    81120u
#define KSEL    512u
#define NBOX    1536
#define NWORD   24             // 1536/64 mask words per row
#define BINBASE 0xBF199u       // (bits(0.6)|sign)>>12 ; keys for obj in (0.6,1]
#define NBIN    1640u          // 0xBF800 - 0xBF199 + 1
#define NBINP   1664u          // padded
#define POOLCAP 65536u
#define SORTCAP 4096

typedef unsigned long long u64;
typedef uint32_t u32;

// ---------------- device scratch (static, allocation-free) ----------------
// NOTE: zero-initialized at module load; k_nms_out re-zeroes at the end of
// every run, so every execution starts from zeroed state (deterministic).
__device__ u32   g_hist[3*NBINP];
__device__ u32   g_validCount[3];
__device__ u32   g_selCount[3];
__device__ u32   g_poolCount[3];
__device__ u64   g_sel[3*512];
__device__ u64   g_pool[3*POOLCAP];
__device__ u64   g_sorted[NBOX];
__device__ float g_boxes[NBOX*9];
__device__ float g_nmsb[NBOX*5];     // x1,y1,x2,y2,area
__device__ int   g_valid[NBOX];
__device__ u64   g_mask[NBOX*NWORD];

// ---------------- shared address/key computation ----------------
__device__ __forceinline__ void cand_addr(u32 i,
        const float* __restrict__ o13, const float* __restrict__ o26,
        const float* __restrict__ o52,
        float& x, int& s, u32& orig) {
    if (i < OFF1) {                 // H=13, HW=169, NHW=5408
        u32 loc = i;
        u32 a = loc / 5408u, r = loc - a*5408u;
        u32 n = r / 169u,  hw = r - n*169u;
        x = o13[(n*255u + a*85u)*169u + hw]; s = 0; orig = r*3u + a;
    } else if (i < OFF2) {          // H=26, HW=676, NHW=21632
        u32 loc = i - OFF1;
        u32 a = loc / 21632u, r = loc - a*21632u;
        u32 n = r / 676u,  hw = r - n*676u;
        x = o26[(n*255u + a*85u)*676u + hw]; s = 1; orig = r*3u + a;
    } else {                        // H=52, HW=2704, NHW=86528
        u32 loc = i - OFF2;
        u32 a = loc / 86528u, r = loc - a*86528u;
        u32 n = r / 2704u, hw = r - n*2704u;
        x = o52[(n*255u + a*85u)*2704u + hw]; s = 2; orig = r*3u + a;
    }
}

// ---------------- K1: 1640-bin histogram of score keys ----------------
__global__ __launch_bounds__(256) void k_hist(const float* __restrict__ o13,
                                              const float* __restrict__ o26,
                                              const float* __restrict__ o52) {
    __shared__ u32 sh[3*NBINP];
    __shared__ u32 svc[3];
    for (u32 b = threadIdx.x; b < 3u*NBINP; b += 256u) sh[b] = 0u;
    if (threadIdx.x < 3u) svc[threadIdx.x] = 0u;
    __syncthreads();
    for (u32 i = blockIdx.x*256u + threadIdx.x; i < TOTAL; i += 65536u) {
        float x; int s; u32 orig;
        cand_addr(i, o13, o26, o52, x, s, orig);
        float obj = 1.f / (1.f + expf(-x));
        if (obj > 0.6f) {
            u32 key = __float_as_uint(obj) | 0x80000000u;
            atomicAdd(&sh[(u32)s*NBINP + ((key >> 12) - BINBASE)], 1u);
            atomicAdd(&svc[s], 1u);
        }
    }
    __syncthreads();
    for (u32 b = threadIdx.x; b < 3u*NBINP; b += 256u) {
        u32 v = sh[b];
        if (v) atomicAdd(&g_hist[b], v);
    }
    if (threadIdx.x < 3u && svc[threadIdx.x]) atomicAdd(&g_validCount[threadIdx.x], svc[threadIdx.x]);
}

// ---------------- K2: recompute keys; direct-select above threshold bin,
//                  pool the threshold bin. Threshold bin found per block
//                  by a redundant in-smem suffix scan of the global hist. ----
__global__ __launch_bounds__(256) void k_select(const float* __restrict__ o13,
                                                const float* __restrict__ o26,
                                                const float* __restrict__ o52) {
    __shared__ u32 ss[256];
    __shared__ int shBin[3];
    __shared__ u32 t_unused;
    const u32 t = threadIdx.x;
    // per-scale threshold-bin scan (block-redundant, uniform branches)
    for (int s = 0; s < 3; s++) {
        if (g_validCount[s] < KSEL) {
            if (t == 0) shBin[s] = -2;            // select every valid directly
        } else {
            u32 b0 = t * 7u;
            u32 part = 0u;
            #pragma unroll
            for (u32 k = 0; k < 7u; k++) {
                u32 b = b0 + k;
                if (b < NBIN) part += g_hist[(u32)s*NBINP + b];
            }
            ss[t] = part;
            __syncthreads();
            for (u32 off = 1; off < 256u; off <<= 1) {   // inclusive suffix scan
                u32 add = (t + off < 256u) ? ss[t + off] : 0u;
                __syncthreads();
                ss[t] += add;
                __syncthreads();
            }
            u32 S = ss[t];
            u32 Sn = (t < 255u) ? ss[t + 1] : 0u;
            if (S >= KSEL && Sn < KSEL) {
                u32 cum = Sn;
                for (int k = 6; k >= 0; k--) {
                    u32 b = b0 + (u32)k;
                    if (b < NBIN) {
                        u32 c = g_hist[(u32)s*NBINP + b];
                        cum += c;
                        if (cum >= KSEL) { shBin[s] = (int)b; break; }
                    }
                }
            }
        }
        __syncthreads();
    }
    const int b0 = shBin[0], b1 = shBin[1], b2 = shBin[2];
    for (u32 i = blockIdx.x*256u + t; i < TOTAL; i += 65536u) {
        float x; int s; u32 orig;
        cand_addr(i, o13, o26, o52, x, s, orig);
        float obj = 1.f / (1.f + expf(-x));
        if (!(obj > 0.6f)) continue;
        u32 key = __float_as_uint(obj) | 0x80000000u;
        int hidx = (int)((key >> 12) - BINBASE);
        int tb = (s == 0) ? b0 : (s == 1) ? b1 : b2;
        if (hidx > tb) {
            u32 pos = atomicAdd(&g_selCount[s], 1u);
            g_sel[(u32)s*512u + pos] = ((u64)key << 32) | orig;
        } else if (hidx == tb) {
            u32 pos = atomicAdd(&g_poolCount[s], 1u);
            if (pos < POOLCAP)
                g_pool[(u32)s*POOLCAP + pos] = ((u64)key << 32) | (u32)(~orig);
        }
    }
    (void)t_unused;
}

// ---------------- K3: threshold-bin top-off + global bitonic sort ----------------
__global__ __launch_bounds__(1024) void k_sortfix() {
    __shared__ u64 sm[SORTCAP];        // 32 KB, reused
    __shared__ u32 sTot[3];
    __shared__ u32 scnt, srank;
    const u32 t = threadIdx.x;
    for (int s = 0; s < 3; s++) {
        u32 direct = g_selCount[s];
        u32 valid  = g_validCount[s];
        u32 need   = (valid >= KSEL) ? (KSEL - direct) : 0u;
        if (t == 0) sTot[s] = direct + need;
        u32 n = g_poolCount[s]; if (n > POOLCAP) n = POOLCAP;
        if (need > 0u) {
            if (n <= (u32)SORTCAP) {
                u32 P = 2u; while (P < n) P <<= 1u;
                for (u32 i = t; i < P; i += 1024u)
                    sm[i] = (i < n) ? g_pool[(u32)s*POOLCAP + i] : 0ull;
                __syncthreads();
                for (u32 k = 2; k <= P; k <<= 1)
                    for (u32 j = k >> 1; j > 0; j >>= 1) {
                        for (u32 i = t; i < P; i += 1024u) {
                            u32 ixj = i ^ j;
                            if (ixj > i) {
                                bool desc = ((i & k) == 0u);
                                u64 x = sm[i], y = sm[ixj];
                                if (desc ? (x < y) : (x > y)) { sm[i] = y; sm[ixj] = x; }
                            }
                        }
                        __syncthreads();
                    }
                for (u32 j = t; j < need; j += 1024u) {
                    u64 v = sm[j];
                    g_sel[(u32)s*512u + direct + j] =
                        (v & 0xFFFFFFFF00000000ull) | (u32)(~(u32)v);
                }
            } else {
                // fallback: exact selection via 64-bit binary search (v unique)
                u64 lo = 1ull, hi = 0xFFFFFFFFFFFFFFFFull;
                while (lo < hi) {
                    u64 mid = lo + ((hi - lo + 1ull) >> 1);
                    if (t == 0) scnt = 0u;
                    __syncthreads();
                    u32 c = 0u;
                    for (u32 j = t; j < n; j += 1024u)
                        if (g_pool[(u32)s*POOLCAP + j] >= mid) c++;
                    if (c) atomicAdd(&scnt, c);
                    __syncthreads();
                    u32 total = scnt;
                    __syncthreads();
                    if (total >= need) lo = mid; else hi = mid - 1ull;
                }
                if (t == 0) srank = 0u;
                __syncthreads();
                for (u32 j = t; j < n; j += 1024u) {
                    u64 v = g_pool[(u32)s*POOLCAP + j];
                    if (v >= lo) {
                        u32 p = atomicAdd(&srank, 1u);
                        if (p < need)
                            g_sel[(u32)s*512u + direct + p] =
                                (v & 0xFFFFFFFF00000000ull) | (u32)(~(u32)v);
                    }
                }
            }
        }
        __syncthreads();
    }
    // ---- global sort: 2048-entry bitonic (score desc, concat-pos asc) ----
    const u32 offc[3] = {0u, OFF1, OFF2};
    for (u32 j = t; j < 2048u; j += 1024u) {
        u64 v = 0ull;
        if (j < (u32)NBOX) {
            u32 s = j >> 9, p = j & 511u;
            if (p < sTot[s]) {
                u64 e = g_sel[s*512u + p];
                u32 key  = (u32)(e >> 32);
                u32 gidx = offc[s] + (u32)e;
                v = ((u64)key << 32) | (u32)(~gidx);
            }
        }
        sm[j] = v;
    }
    __syncthreads();
    for (u32 k = 2; k <= 2048u; k <<= 1)
        for (u32 j = k >> 1; j > 0; j >>= 1) {
            for (u32 i = t; i < 2048u; i += 1024u) {
                u32 ixj = i ^ j;
                if (ixj > i) {
                    bool desc = ((i & k) == 0u);
                    u64 x = sm[i], y = sm[ixj];
                    if (desc ? (x < y) : (x > y)) { sm[i] = y; sm[ixj] = x; }
                }
            }
            __syncthreads();
        }
    for (u32 j = t; j < (u32)NBOX; j += 1024u) g_sorted[j] = sm[j];
}

// ---------------- K4: decode winners (one warp per box) ----------------
__global__ void k_decode(const float* __restrict__ o13, const float* __restrict__ o26,
                         const float* __restrict__ o52,
                         const float* __restrict__ a13, const float* __restrict__ a26,
                         const float* __restrict__ a52) {
    int r = (blockIdx.x * blockDim.x + threadIdx.x) >> 5;
    int lane = threadIdx.x & 31;
    if (r >= NBOX) return;
    u64 e = g_sorted[r];
    u32 key = (u32)(e >> 32);
    if (key == 0u) {
        if (lane == 0) {
            #pragma unroll
            for (int k = 0; k < 9; k++) g_boxes[r*9+k] = 0.f;
            #pragma unroll
            for (int k = 0; k < 5; k++) g_nmsb[r*5+k] = 0.f;
            g_valid[r] = 0;
        }
        return;
    }
    u32 gidx = ~(u32)e;
    const float* p; const float* anc; int H; float ts; u32 loc;
    if (gidx < OFF1)      { p=o13; anc=a13; H=13; ts=32.f; loc=gidx; }
    else if (gidx < OFF2) { p=o26; anc=a26; H=26; ts=16.f; loc=gidx-OFF1; }
    else                  { p=o52; anc=a52; H=52; ts=8.f;  loc=gidx-OFF2; }
    u32 a = loc % 3u; u32 q = loc / 3u;
    u32 w = q % (u32)H; q /= (u32)H;
    u32 h = q % (u32)H; u32 n = q / (u32)H;
    int HW = H*H;
    const float* base = p + (size_t)(n*255u + a*85u)*HW + h*H + w;
    float bv = -1e30f; int bc = 1 << 30;       // argmax 80 classes, first-max
    for (int c = lane; c < 80; c += 32) {
        float v = base[(5 + c) * HW];
        if (v > bv) { bv = v; bc = c; }
    }
    #pragma unroll
    for (int off = 16; off; off >>= 1) {
        float ov = __shfl_down_sync(0xffffffffu, bv, off);
        int   oc = __shfl_down_sync(0xffffffffu, bc, off);
        if (ov > bv || (ov == bv && oc < bc)) { bv = ov; bc = oc; }
    }
    if (lane == 0) {
        float v1 = base[HW], v2 = base[2*HW], v3 = base[3*HW], v4 = base[4*HW];
        float obj = __uint_as_float(key ^ 0x80000000u);
        float cx = ((float)w + v1) * ts / 416.0f;
        float cy = ((float)h + v2) * ts / 416.0f;
        float bw = anc[a*2+0] * expf(v3) / 416.0f;
        float bh = anc[a*2+1] * expf(v4) / 416.0f;
        float* B = &g_boxes[r*9];
        B[0]=(float)n; B[1]=cx; B[2]=cy; B[3]=bw; B[4]=bh;
        B[5]=obj; B[6]=(float)bc; B[7]=(float)h; B[8]=(float)w;
        float x1 = cx - bw*0.5f, y1 = cy - bh*0.5f;
        float x2 = cx + bw*0.5f, y2 = cy + bh*0.5f;
        float area = fmaxf(x2-x1, 0.f) * fmaxf(y2-y1, 0.f);
        float* Nn = &g_nmsb[r*5];
        Nn[0]=x1; Nn[1]=y1; Nn[2]=x2; Nn[3]=y2; Nn[4]=area;
        g_valid[r] = 1;
    }
}

// ---------------- K5: suppression bitmask (iou inter/min > 0.7, col > row) ----------------
__global__ void k_mask() {
    int cb = blockIdx.x, rb = blockIdx.y;
    __shared__ float c0[64], c1[64], c2[64], c3[64], ca[64];
    int t = threadIdx.x;
    int c = cb*64 + t;
    c0[t]=g_nmsb[c*5+0]; c1[t]=g_nmsb[c*5+1]; c2[t]=g_nmsb[c*5+2];
    c3[t]=g_nmsb[c*5+3]; ca[t]=g_nmsb[c*5+4];
    __syncthreads();
    int r = rb*64 + t;
    float x1=g_nmsb[r*5+0], y1=g_nmsb[r*5+1], x2=g_nmsb[r*5+2],
          y2=g_nmsb[r*5+3], ar=g_nmsb[r*5+4];
    u64 bits = 0ull;
    #pragma unroll 4
    for (int j = 0; j < 64; j++) {
        int cc = cb*64 + j;
        if (cc > r) {
            float ix = fmaxf(fminf(x2, c2[j]) - fmaxf(x1, c0[j]), 0.f);
            float iy = fmaxf(fminf(y2, c3[j]) - fmaxf(y1, c1[j]), 0.f);
            float iou = (ix * iy) / fmaxf(fminf(ar, ca[j]), 1e-9f);
            if (iou > 0.7f) bits |= (1ull << j);
        }
    }
    g_mask[r*NWORD + cb] = bits;
}

// ---------------- K6: greedy scan + masked output + state re-zero ----------------
__global__ __launch_bounds__(256) void k_nms_out(float* __restrict__ out) {
    __shared__ u64 tile[2][64*NWORD];      // 2 x 12 KB
    __shared__ u64 svalidw[NWORD];
    __shared__ u64 skeep[NWORD];
    int tid = threadIdx.x;
    // re-zero selection state for the NEXT run (globals start zeroed at load)
    for (u32 z = tid; z < 3u*NBINP; z += 256u) g_hist[z] = 0u;
    if (tid < 3) { g_validCount[tid]=0u; g_selCount[tid]=0u; g_poolCount[tid]=0u; }
    if (tid < NWORD) {
        u64 v = 0ull;
        for (int j = 0; j < 64; j++) if (g_valid[tid*64 + j]) v |= 1ull << j;
        svalidw[tid] = v;
    }
    for (int k = tid; k < 64*NWORD; k += 256)
        tile[0][k] = g_mask[k];
    __syncthreads();
    u64 remv = 0ull;                        // lane w (w<NWORD) holds remv word w
    for (int c = 0; c < NWORD; c++) {
        if (tid >= 32 && c + 1 < NWORD) {   // prefetch next chunk
            for (int k = tid - 32; k < 64*NWORD; k += 224)
                tile[(c+1)&1][k] = g_mask[(size_t)(c+1)*(64*NWORD) + k];
        }
        if (tid < 32) {
            u64* T = tile[c&1];
            u64 cur = __shfl_sync(0xffffffffu, remv, c);
            u64 keptbits = 0ull;
            if (tid == 0) {
                u64 validw = svalidw[c];
                u64 rows[64];
                #pragma unroll
                for (int j = 0; j < 64; j++) rows[j] = T[j*NWORD + c];
                #pragma unroll
                for (int j = 0; j < 64; j++) {
                    u64 b = 1ull << j;
                    if ((validw & b) && !(cur & b)) { cur |= rows[j]; keptbits |= b; }
                }
                skeep[c] = keptbits;
            }
            keptbits = __shfl_sync(0xffffffffu, keptbits, 0);
            if (tid < NWORD) {
                u64 kb = keptbits, acc = 0ull;
                while (kb) {
                    int j = __ffsll((long long)kb) - 1;
                    kb &= kb - 1ull;
                    acc |= T[j*NWORD + tid];
                }
                remv |= acc;
            }
        }
        __syncthreads();
    }
    for (int e = tid; e < NBOX*9; e += 256) {
        int r = e / 9;
        out[e] = g_boxes[e] * (((skeep[r >> 6] >> (r & 63)) & 1ull) ? 1.f : 0.f);
    }
}

// ---------------- launcher: 6 graph nodes ----------------
extern "C" void kernel_launch(void* const* d_in, const int* in_sizes, int n_in,
                              void* d_out, int out_size) {
    const float* o13 = (const float*)d_in[0];
    const float* o26 = (const float*)d_in[1];
    const float* o52 = (const float*)d_in[2];
    const float* a13 = (const float*)d_in[3];
    const float* a26 = (const float*)d_in[4];
    const float* a52 = (const float*)d_in[5];
    float* out = (float*)d_out;

    k_hist   <<<256, 256>>>(o13, o26, o52);
    k_select <<<256, 256>>>(o13, o26, o52);
    k_sortfix<<<1, 1024>>>();
    k_decode <<<192, 256>>>(o13, o26, o52, a13, a26, a52);
    k_mask   <<<dim3(24,24), 64>>>();
    k_nms_out<<<1, 256>>>(out);
    (void)in_sizes; (void)n_in; (void)out_size;
}